// round 3
// baseline (speedup 1.0000x reference)
#include <cuda_runtime.h>

#define FULLMASK 0xffffffffu

constexpr int B = 64;
constexpr int L = 512;
constexpr int R = 1024;
constexpr int A = 14;
constexpr float EPSV = 1e-12f;
constexpr float CUT2 = 25.0f;   // CUTOFF^2

// -------- scratch (device globals; no allocations allowed) --------
__device__ float g_lig_num[B];
__device__ float g_lig_den[B];
__device__ float g_lig_se[B];
__device__ float g_lig_cnt[B];
__device__ float g_acc[4];   // 0: sc_dist_sum, 1: sc_dist_cnt, 2: sc_mse_num, 3: sc_mse_den

// upper-triangle pair table for A=14, packed (i<<4)|j, 91 valid + pad
__device__ const unsigned char d_pairs[96] = {
    0x01,0x02,0x03,0x04,0x05,0x06,0x07,0x08,0x09,0x0A,0x0B,0x0C,0x0D,
    0x12,0x13,0x14,0x15,0x16,0x17,0x18,0x19,0x1A,0x1B,0x1C,0x1D,
    0x23,0x24,0x25,0x26,0x27,0x28,0x29,0x2A,0x2B,0x2C,0x2D,
    0x34,0x35,0x36,0x37,0x38,0x39,0x3A,0x3B,0x3C,0x3D,
    0x45,0x46,0x47,0x48,0x49,0x4A,0x4B,0x4C,0x4D,
    0x56,0x57,0x58,0x59,0x5A,0x5B,0x5C,0x5D,
    0x67,0x68,0x69,0x6A,0x6B,0x6C,0x6D,
    0x78,0x79,0x7A,0x7B,0x7C,0x7D,
    0x89,0x8A,0x8B,0x8C,0x8D,
    0x9A,0x9B,0x9C,0x9D,
    0xAB,0xAC,0xAD,
    0xBC,0xBD,
    0xCD,
    0,0,0,0,0
};

__device__ __forceinline__ float fast_sqrt(float x) {
    float r;
    asm("sqrt.approx.f32 %0, %1;" : "=f"(r) : "f"(x));
    return r;
}

__global__ void zero_kernel() {
    int t = threadIdx.x;
    if (t < B) {
        g_lig_num[t] = 0.f; g_lig_den[t] = 0.f;
        g_lig_se[t]  = 0.f; g_lig_cnt[t] = 0.f;
    }
    if (t < 4) g_acc[t] = 0.f;
}

// ---------------- ligand: coord loss + pairwise distance loss ----------------
// grid = B*8 blocks, 256 threads. Block = (batch b, tile of 64 i-rows).
// Round-robin pairing: unordered pairs (i, (i+k) mod 512), k=1..255 all i,
// k=256 only for i<256 -> each unordered pair exactly once, uniform load.
__global__ void __launch_bounds__(256) ligand_kernel(
    const float* __restrict__ pred, const float* __restrict__ tgt,
    const unsigned int* __restrict__ mask)   // bool serialized as 32-bit words
{
    __shared__ float4 sp[L];   // xyz + |x|^2
    __shared__ float4 st[L];
    __shared__ float  sm[L];

    const int b = blockIdx.x >> 3;
    const int tile = blockIdx.x & 7;
    const float* P = pred + (size_t)b * L * 3;
    const float* T = tgt  + (size_t)b * L * 3;
    const unsigned int* M = mask + (size_t)b * L;
    const int t = threadIdx.x;

    for (int j = t; j < L; j += 256) {
        float px = P[j*3+0], py = P[j*3+1], pz = P[j*3+2];
        float tx = T[j*3+0], ty = T[j*3+1], tz = T[j*3+2];
        sp[j] = make_float4(px, py, pz, px*px + py*py + pz*pz);
        st[j] = make_float4(tx, ty, tz, tx*tx + ty*ty + tz*tz);
        sm[j] = (M[j] != 0u) ? 1.f : 0.f;   // works for int32 and float32 bools
    }
    __syncthreads();

    const int i   = tile * 64 + (t & 63);
    const int off = t >> 6;                 // 0..3
    const float4 pi = sp[i];
    const float4 ti = st[i];
    const float  mi = sm[i];

    float num = 0.f, den = 0.f;
    #pragma unroll 4
    for (int k = 1 + off; k <= 256; k += 4) {
        if (k == 256 && i >= 256) break;    // k=256 pairs counted once (i<256)
        int j = (i + k) & (L - 1);
        float4 pj = sp[j], tj = st[j];
        float  mj = sm[j];
        float dp = pi.x*pj.x; dp = fmaf(pi.y, pj.y, dp); dp = fmaf(pi.z, pj.z, dp);
        float dt = ti.x*tj.x; dt = fmaf(ti.y, tj.y, dt); dt = fmaf(ti.z, tj.z, dt);
        float psq = fmaf(-2.f, dp, pi.w + pj.w);
        float tsq = fmaf(-2.f, dt, ti.w + tj.w);
        float w = (tsq > 0.f && tsq <= CUT2) ? mi * mj : 0.f;
        float pe = fmaxf(psq, EPSV);
        float te = fmaxf(tsq, EPSV);
        float v  = pe + te - 2.f * fast_sqrt(pe * te);   // (pd - td)^2
        num = fmaf(w, v, num);
        den += w;
    }

    // per-batch coordinate MSE (each row handled by its off==0 thread)
    float se = 0.f, cnt = 0.f;
    if (off == 0) {
        float dx = pi.x - ti.x, dy = pi.y - ti.y, dz = pi.z - ti.z;
        se  = mi * (dx*dx + dy*dy + dz*dz);
        cnt = mi;
    }

    const int lane = t & 31;
    #pragma unroll
    for (int s = 16; s > 0; s >>= 1) {
        num += __shfl_down_sync(FULLMASK, num, s);
        den += __shfl_down_sync(FULLMASK, den, s);
        se  += __shfl_down_sync(FULLMASK, se,  s);
        cnt += __shfl_down_sync(FULLMASK, cnt, s);
    }
    __shared__ float4 wr[8];
    if (lane == 0) wr[t >> 5] = make_float4(num, den, se, cnt);
    __syncthreads();
    if (t < 8) {
        float4 v4 = wr[t];
        float a0 = v4.x, a1 = v4.y, a2 = v4.z, a3 = v4.w;
        #pragma unroll
        for (int s = 4; s > 0; s >>= 1) {
            a0 += __shfl_down_sync(0xffu, a0, s);
            a1 += __shfl_down_sync(0xffu, a1, s);
            a2 += __shfl_down_sync(0xffu, a2, s);
            a3 += __shfl_down_sync(0xffu, a3, s);
        }
        if (t == 0) {
            atomicAdd(&g_lig_num[b], a0);
            atomicAdd(&g_lig_den[b], a1);
            atomicAdd(&g_lig_se[b],  a2);
            atomicAdd(&g_lig_cnt[b], a3);
        }
    }
}

// ---------------- sidechain: per-residue dist loss + global atom MSE ----------------
// one warp per (b,r) group of 14 atoms; 8 groups per 256-thread block
__global__ void __launch_bounds__(256) sidechain_kernel(
    const float* __restrict__ pred, const float* __restrict__ tgt,
    const unsigned int* __restrict__ mask)   // bool serialized as 32-bit words
{
    __shared__ float sp[8][64];   // [atom*4 + comp], comp 3 = |x|^2
    __shared__ float st[8][64];
    __shared__ float sm[8][16];
    __shared__ float bacc[4];

    const int t = threadIdx.x;
    if (t < 4) bacc[t] = 0.f;
    const int w = t >> 5, lane = t & 31;
    const unsigned int g = blockIdx.x * 8 + w;     // group id < B*R
    const float* P = pred + (size_t)g * (A * 3);
    const float* T = tgt  + (size_t)g * (A * 3);
    float* spw = sp[w];
    float* stw = st[w];

    for (int k = lane; k < A * 3; k += 32) {
        int a = k / 3, c = k - a * 3;
        spw[a * 4 + c] = P[k];
        stw[a * 4 + c] = T[k];
    }
    __syncwarp();
    if (lane < A) {
        float x = spw[lane*4], y = spw[lane*4+1], z = spw[lane*4+2];
        spw[lane*4+3] = x*x + y*y + z*z;
        x = stw[lane*4]; y = stw[lane*4+1]; z = stw[lane*4+2];
        stw[lane*4+3] = x*x + y*y + z*z;
        sm[w][lane] = (mask[(size_t)g * A + lane] != 0u) ? 1.f : 0.f;
    }
    __syncwarp();

    const float4* sp4 = (const float4*)spw;
    const float4* st4 = (const float4*)stw;
    float num = 0.f, den = 0.f;
    #pragma unroll
    for (int it = 0; it < 3; ++it) {
        int p = lane + it * 32;
        if (p < 91) {
            int code = d_pairs[p];
            int i = code >> 4, j = code & 15;
            float4 pi = sp4[i], pj = sp4[j];
            float4 ti = st4[i], tj = st4[j];
            float dp = pi.x*pj.x; dp = fmaf(pi.y, pj.y, dp); dp = fmaf(pi.z, pj.z, dp);
            float dt = ti.x*tj.x; dt = fmaf(ti.y, tj.y, dt); dt = fmaf(ti.z, tj.z, dt);
            float psq = fmaf(-2.f, dp, pi.w + pj.w);
            float tsq = fmaf(-2.f, dt, ti.w + tj.w);
            float ww = (tsq > 0.f && tsq <= CUT2) ? sm[w][i] * sm[w][j] : 0.f;
            float pe = fmaxf(psq, EPSV), te = fmaxf(tsq, EPSV);
            float v = pe + te - 2.f * fast_sqrt(pe * te);
            num = fmaf(ww, v, num);
            den += ww;
        }
    }

    // per-atom MSE (mean over 3 coords)
    float mnum = 0.f, mden = 0.f;
    if (lane < A) {
        float dx = spw[lane*4]   - stw[lane*4];
        float dy = spw[lane*4+1] - stw[lane*4+1];
        float dz = spw[lane*4+2] - stw[lane*4+2];
        float m = sm[w][lane];
        mnum = m * (dx*dx + dy*dy + dz*dz) * (1.f / 3.f);
        mden = m;
    }

    #pragma unroll
    for (int s = 16; s > 0; s >>= 1) {
        num  += __shfl_down_sync(FULLMASK, num,  s);
        den  += __shfl_down_sync(FULLMASK, den,  s);
        mnum += __shfl_down_sync(FULLMASK, mnum, s);
        mden += __shfl_down_sync(FULLMASK, mden, s);
    }

    __syncthreads();   // orders bacc zeroing before warp atomics
    if (lane == 0) {
        float gs = 0.f, gc = 0.f;
        if (den > 0.f) { gs = num / den; gc = 1.f; }  // den>=1 when >0 -> max(den,1)=den
        atomicAdd(&bacc[0], gs);
        atomicAdd(&bacc[1], gc);
        atomicAdd(&bacc[2], mnum);
        atomicAdd(&bacc[3], mden);
    }
    __syncthreads();
    if (t < 4) atomicAdd(&g_acc[t], bacc[t]);
}

// ---------------- finalize ----------------
__global__ void finalize_kernel(float* out, int out_size) {
    const int t = threadIdx.x;   // 64 threads
    float lig = g_lig_se[t] / (3.f * fmaxf(g_lig_cnt[t], 1.f));
    float den = g_lig_den[t];
    float has = den > 0.f ? 1.f : 0.f;
    float ld  = (den > 0.f) ? g_lig_num[t] / den : 0.f;

    const int lane = t & 31;
    #pragma unroll
    for (int s = 16; s > 0; s >>= 1) {
        lig += __shfl_down_sync(FULLMASK, lig, s);
        ld  += __shfl_down_sync(FULLMASK, ld,  s);
        has += __shfl_down_sync(FULLMASK, has, s);
    }
    __shared__ float sh[3][2];
    if (lane == 0) { sh[0][t>>5] = lig; sh[1][t>>5] = ld; sh[2][t>>5] = has; }
    __syncthreads();
    if (t == 0) {
        float ligand_loss = (sh[0][0] + sh[0][1]) / 64.f;
        float hs = sh[2][0] + sh[2][1];
        float ligand_dist = (sh[1][0] + sh[1][1]) / fmaxf(hs, 1.f);
        float sc  = g_acc[2] / fmaxf(g_acc[3], 1.f);
        float scd = g_acc[0] / fmaxf(g_acc[1], 1.f);
        float total = ligand_loss + 0.2f * ligand_dist + 0.5f * sc + 0.1f * scd;
        for (int k = 0; k < out_size; ++k) out[k] = total;
    }
}

extern "C" void kernel_launch(void* const* d_in, const int* in_sizes, int n_in,
                              void* d_out, int out_size) {
    const float* lp  = (const float*)d_in[0];
    const float* lt  = (const float*)d_in[1];
    const float* scp = (const float*)d_in[2];
    const float* sct = (const float*)d_in[3];
    const unsigned int* lm = (const unsigned int*)d_in[4];
    const unsigned int* am = (const unsigned int*)d_in[5];
    (void)in_sizes; (void)n_in;

    zero_kernel<<<1, 64>>>();
    ligand_kernel<<<B * 8, 256>>>(lp, lt, lm);
    sidechain_kernel<<<(B * R) / 8, 256>>>(scp, sct, am);
    finalize_kernel<<<1, 64>>>((float*)d_out, out_size);
}

// round 4
// speedup vs baseline: 1.1720x; 1.1720x over previous
#include <cuda_runtime.h>

#define FULLMASK 0xffffffffu

constexpr int B = 64;
constexpr int L = 512;
constexpr int R = 1024;
constexpr int A = 14;
constexpr float EPSV = 1e-12f;
constexpr float CUT2 = 25.0f;     // CUTOFF^2

constexpr int LIG_BLOCKS = B * 8;          // 512
constexpr int SC_GROUPS_PER_BLOCK = 8;
constexpr int SC_BLOCKS = (B * R) / SC_GROUPS_PER_BLOCK;   // 8192
constexpr int GRID = LIG_BLOCKS + SC_BLOCKS;               // 8704
constexpr int NSLOT = 32;

// -------- persistent scratch (zero at module load; finalizer re-zeros each run) --------
__device__ float g_lig_num[B];
__device__ float g_lig_den[B];
__device__ float g_lig_se[B];
__device__ float g_lig_cnt[B];
__device__ float g_slots[4][NSLOT];   // 0: sc_dist_sum, 1: sc_dist_cnt, 2: sc_mse_num, 3: sc_mse_den
__device__ unsigned int g_ticket;

// upper-triangle pair table for A=14, packed (i<<4)|j, 91 valid + pad
__device__ const unsigned char d_pairs[96] = {
    0x01,0x02,0x03,0x04,0x05,0x06,0x07,0x08,0x09,0x0A,0x0B,0x0C,0x0D,
    0x12,0x13,0x14,0x15,0x16,0x17,0x18,0x19,0x1A,0x1B,0x1C,0x1D,
    0x23,0x24,0x25,0x26,0x27,0x28,0x29,0x2A,0x2B,0x2C,0x2D,
    0x34,0x35,0x36,0x37,0x38,0x39,0x3A,0x3B,0x3C,0x3D,
    0x45,0x46,0x47,0x48,0x49,0x4A,0x4B,0x4C,0x4D,
    0x56,0x57,0x58,0x59,0x5A,0x5B,0x5C,0x5D,
    0x67,0x68,0x69,0x6A,0x6B,0x6C,0x6D,
    0x78,0x79,0x7A,0x7B,0x7C,0x7D,
    0x89,0x8A,0x8B,0x8C,0x8D,
    0x9A,0x9B,0x9C,0x9D,
    0xAB,0xAC,0xAD,
    0xBC,0xBD,
    0xCD,
    0,0,0,0,0
};

__device__ __forceinline__ float fast_sqrt(float x) {
    float r;
    asm("sqrt.approx.f32 %0, %1;" : "=f"(r) : "f"(x));
    return r;
}

__global__ void __launch_bounds__(256) fused_kernel(
    const float* __restrict__ lp, const float* __restrict__ lt,
    const float* __restrict__ scp, const float* __restrict__ sct,
    const unsigned int* __restrict__ lm, const unsigned int* __restrict__ am,
    float* __restrict__ out, int out_size)
{
    __shared__ union SU {
        struct { float4 sp[L]; float4 st[L]; } lig;                       // 16 KB
        struct { float sp[8][64]; float st[8][64]; } sc;                  //  4 KB
    } u;
    __shared__ float4 wr[8];
    __shared__ float bacc[4];
    __shared__ unsigned int s_islast;
    __shared__ float fin[3][2];
    __shared__ float sl[4];

    const int t = threadIdx.x;
    const int bid = blockIdx.x;
    const int lane = t & 31;

    if (bid < LIG_BLOCKS) {
        // ================= ligand: coord MSE + pairwise dist loss =================
        const int b = bid >> 3;
        const int tile = bid & 7;
        const float* P = lp + (size_t)b * L * 3;
        const float* T = lt + (size_t)b * L * 3;
        const unsigned int* M = lm + (size_t)b * L;

        float se = 0.f, cnt = 0.f;
        for (int j = t; j < L; j += 256) {
            float px = P[j*3+0], py = P[j*3+1], pz = P[j*3+2];
            float tx = T[j*3+0], ty = T[j*3+1], tz = T[j*3+2];
            bool m = (M[j] != 0u);
            if (tile == 0 && m) {   // coord MSE computed once per batch (tile 0)
                float dx = px - tx, dy = py - ty, dz = pz - tz;
                se  += dx*dx + dy*dy + dz*dz;
                cnt += 1.f;
            }
            // mask trick: push invalid TARGETS far away with >CUTOFF spacing so
            // every pair touching them fails td<=CUTOFF automatically.
            if (!m) tx += 1e4f + 16.f * (float)j;
            u.lig.sp[j] = make_float4(px, py, pz, px*px + py*py + pz*pz);
            u.lig.st[j] = make_float4(tx, ty, tz, tx*tx + ty*ty + tz*tz);
        }
        __syncthreads();

        // round-robin unordered pairing: (i, (i+k) mod 512), k=1..255 all i,
        // k=256 only for i<256 -> each unordered pair exactly once.
        const int i   = tile * 64 + (t & 63);
        const int off = t >> 6;                 // 0..3
        const float4 pi = u.lig.sp[i];
        const float4 ti = u.lig.st[i];

        float num = 0.f, den = 0.f;
        #pragma unroll 4
        for (int k = 1 + off; k <= 256; k += 4) {
            if (k == 256 && i >= 256) break;
            int j = (i + k) & (L - 1);
            float4 pj = u.lig.sp[j], tj = u.lig.st[j];
            float dp = pi.x*pj.x; dp = fmaf(pi.y, pj.y, dp); dp = fmaf(pi.z, pj.z, dp);
            float dt = ti.x*tj.x; dt = fmaf(ti.y, tj.y, dt); dt = fmaf(ti.z, tj.z, dt);
            float psq = fmaf(-2.f, dp, pi.w + pj.w);
            float tsq = fmaf(-2.f, dt, ti.w + tj.w);
            float pe = fmaxf(psq, EPSV);
            float te = fmaxf(tsq, EPSV);
            float v  = pe + te - 2.f * fast_sqrt(pe * te);   // (pd - td)^2
            if (tsq > 0.f && tsq <= CUT2) { num += v; den += 1.f; }
        }

        #pragma unroll
        for (int s = 16; s > 0; s >>= 1) {
            num += __shfl_down_sync(FULLMASK, num, s);
            den += __shfl_down_sync(FULLMASK, den, s);
            se  += __shfl_down_sync(FULLMASK, se,  s);
            cnt += __shfl_down_sync(FULLMASK, cnt, s);
        }
        if (lane == 0) wr[t >> 5] = make_float4(num, den, se, cnt);
        __syncthreads();
        if (t < 8) {
            float4 v4 = wr[t];
            float a0 = v4.x, a1 = v4.y, a2 = v4.z, a3 = v4.w;
            #pragma unroll
            for (int s = 4; s > 0; s >>= 1) {
                a0 += __shfl_down_sync(0xffu, a0, s);
                a1 += __shfl_down_sync(0xffu, a1, s);
                a2 += __shfl_down_sync(0xffu, a2, s);
                a3 += __shfl_down_sync(0xffu, a3, s);
            }
            if (t == 0) {
                atomicAdd(&g_lig_num[b], a0);
                atomicAdd(&g_lig_den[b], a1);
                atomicAdd(&g_lig_se[b],  a2);
                atomicAdd(&g_lig_cnt[b], a3);
            }
        }
    } else {
        // ================= sidechain: per-residue dist loss + global atom MSE =================
        if (t < 4) bacc[t] = 0.f;
        const int w = t >> 5;
        const unsigned int g = (unsigned int)(bid - LIG_BLOCKS) * SC_GROUPS_PER_BLOCK + w;
        const float* P = scp + (size_t)g * (A * 3);
        const float* T = sct + (size_t)g * (A * 3);
        float* spw = u.sc.sp[w];
        float* stw = u.sc.st[w];

        for (int k = lane; k < A * 3; k += 32) {
            int a = k / 3, c = k - a * 3;
            spw[a * 4 + c] = P[k];
            stw[a * 4 + c] = T[k];
        }
        __syncwarp();

        float mnum = 0.f, mden = 0.f;
        if (lane < A) {
            float px = spw[lane*4], py = spw[lane*4+1], pz = spw[lane*4+2];
            float tx = stw[lane*4], ty = stw[lane*4+1], tz = stw[lane*4+2];
            float m = (am[(size_t)g * A + lane] != 0u) ? 1.f : 0.f;
            float dx = px - tx, dy = py - ty, dz = pz - tz;
            mnum = m * (dx*dx + dy*dy + dz*dz) * (1.f / 3.f);
            mden = m;
            if (m == 0.f) {                      // mask trick on target
                tx += 1e3f + 16.f * (float)lane;
                stw[lane*4] = tx;
            }
            spw[lane*4+3] = px*px + py*py + pz*pz;
            stw[lane*4+3] = tx*tx + ty*ty + tz*tz;
        }
        __syncwarp();

        const float4* sp4 = (const float4*)spw;
        const float4* st4 = (const float4*)stw;
        float num = 0.f, den = 0.f;
        #pragma unroll
        for (int it = 0; it < 3; ++it) {
            int p = lane + it * 32;
            if (p < 91) {
                int code = d_pairs[p];
                int i = code >> 4, j = code & 15;
                float4 pi = sp4[i], pj = sp4[j];
                float4 ti = st4[i], tj = st4[j];
                float dp = pi.x*pj.x; dp = fmaf(pi.y, pj.y, dp); dp = fmaf(pi.z, pj.z, dp);
                float dt = ti.x*tj.x; dt = fmaf(ti.y, tj.y, dt); dt = fmaf(ti.z, tj.z, dt);
                float psq = fmaf(-2.f, dp, pi.w + pj.w);
                float tsq = fmaf(-2.f, dt, ti.w + tj.w);
                float pe = fmaxf(psq, EPSV), te = fmaxf(tsq, EPSV);
                float v = pe + te - 2.f * fast_sqrt(pe * te);
                if (tsq > 0.f && tsq <= CUT2) { num += v; den += 1.f; }
            }
        }

        #pragma unroll
        for (int s = 16; s > 0; s >>= 1) {
            num  += __shfl_down_sync(FULLMASK, num,  s);
            den  += __shfl_down_sync(FULLMASK, den,  s);
            mnum += __shfl_down_sync(FULLMASK, mnum, s);
            mden += __shfl_down_sync(FULLMASK, mden, s);
        }

        __syncthreads();   // bacc zeroed before warp atomics
        if (lane == 0) {
            float gs = 0.f, gc = 0.f;
            if (den > 0.f) { gs = num / den; gc = 1.f; }
            atomicAdd(&bacc[0], gs);
            atomicAdd(&bacc[1], gc);
            atomicAdd(&bacc[2], mnum);
            atomicAdd(&bacc[3], mden);
        }
        __syncthreads();
        if (t < 4) atomicAdd(&g_slots[t][bid & (NSLOT - 1)], bacc[t]);
    }

    // ================= last-block finalization =================
    __threadfence();
    if (t == 0) s_islast = (atomicAdd(&g_ticket, 1u) == (unsigned)(GRID - 1)) ? 1u : 0u;
    __syncthreads();
    if (!s_islast) return;

    // --- read & reduce (all accumulator writes are globally visible now) ---
    float lig = 0.f, ld = 0.f, has = 0.f;
    if (t < B) {
        float se  = __ldcg(&g_lig_se[t]);
        float cn  = __ldcg(&g_lig_cnt[t]);
        float nu  = __ldcg(&g_lig_num[t]);
        float de  = __ldcg(&g_lig_den[t]);
        lig = se / (3.f * fmaxf(cn, 1.f));
        if (de > 0.f) { ld = nu / de; has = 1.f; }
    }
    #pragma unroll
    for (int s = 16; s > 0; s >>= 1) {
        lig += __shfl_down_sync(FULLMASK, lig, s);
        ld  += __shfl_down_sync(FULLMASK, ld,  s);
        has += __shfl_down_sync(FULLMASK, has, s);
    }
    if (lane == 0 && t < B) { fin[0][t>>5] = lig; fin[1][t>>5] = ld; fin[2][t>>5] = has; }

    if (t < NSLOT) {
        float s0 = __ldcg(&g_slots[0][t]);
        float s1 = __ldcg(&g_slots[1][t]);
        float s2 = __ldcg(&g_slots[2][t]);
        float s3 = __ldcg(&g_slots[3][t]);
        #pragma unroll
        for (int s = 16; s > 0; s >>= 1) {
            s0 += __shfl_down_sync(FULLMASK, s0, s);
            s1 += __shfl_down_sync(FULLMASK, s1, s);
            s2 += __shfl_down_sync(FULLMASK, s2, s);
            s3 += __shfl_down_sync(FULLMASK, s3, s);
        }
        if (t == 0) { sl[0] = s0; sl[1] = s1; sl[2] = s2; sl[3] = s3; }
    }
    __syncthreads();   // reads done before resets

    // --- reset scratch for next graph replay ---
    if (t < B) {
        g_lig_num[t] = 0.f; g_lig_den[t] = 0.f;
        g_lig_se[t]  = 0.f; g_lig_cnt[t] = 0.f;
    }
    if (t < 4 * NSLOT) g_slots[t >> 5][t & (NSLOT - 1)] = 0.f;
    if (t == 1) g_ticket = 0u;

    if (t == 0) {
        float ligand_loss = (fin[0][0] + fin[0][1]) * (1.f / 64.f);
        float hs = fin[2][0] + fin[2][1];
        float ligand_dist = (fin[1][0] + fin[1][1]) / fmaxf(hs, 1.f);
        float sc  = sl[2] / fmaxf(sl[3], 1.f);
        float scd = sl[0] / fmaxf(sl[1], 1.f);
        float total = ligand_loss + 0.2f * ligand_dist + 0.5f * sc + 0.1f * scd;
        for (int k = 0; k < out_size; ++k) out[k] = total;
    }
}

extern "C" void kernel_launch(void* const* d_in, const int* in_sizes, int n_in,
                              void* d_out, int out_size) {
    const float* lp  = (const float*)d_in[0];
    const float* lt  = (const float*)d_in[1];
    const float* scp = (const float*)d_in[2];
    const float* sct = (const float*)d_in[3];
    const unsigned int* lm = (const unsigned int*)d_in[4];
    const unsigned int* am = (const unsigned int*)d_in[5];
    (void)in_sizes; (void)n_in;

    fused_kernel<<<GRID, 256>>>(lp, lt, scp, sct, lm, am, (float*)d_out, out_size);
}

// round 5
// speedup vs baseline: 1.2196x; 1.0406x over previous
#include <cuda_runtime.h>

#define FULLMASK 0xffffffffu

constexpr int B = 64;
constexpr int L = 512;
constexpr int R = 1024;
constexpr int A = 14;
constexpr float EPSV = 1e-12f;
constexpr float CUT2 = 25.0f;     // CUTOFF^2

// ligand: per batch 28 off-diagonal tile-pair blocks + 8 diagonal blocks
constexpr int LIG_BLOCKS_PER_B = 36;
constexpr int LIG_BLOCKS = B * LIG_BLOCKS_PER_B;            // 2304
constexpr int SC_GROUPS_PER_BLOCK = 16;                     // 8 warps x 2 groups
constexpr int SC_BLOCKS = (B * R) / SC_GROUPS_PER_BLOCK;    // 4096
constexpr int GRID = LIG_BLOCKS + SC_BLOCKS;                // 6400
constexpr int NSLOT = 32;

// -------- persistent scratch (zeroed at load; finalizer re-zeros each run) --------
__device__ float g_lig_num[B];
__device__ float g_lig_den[B];
__device__ float g_lig_se[B];
__device__ float g_lig_cnt[B];
__device__ float g_slots[4][NSLOT];
__device__ unsigned int g_ticket;

// off-diagonal tile pair table: (a<<4)|b for 0<=a<b<8, 28 entries
__device__ const unsigned char d_tpairs[28] = {
    0x01,0x02,0x03,0x04,0x05,0x06,0x07,
    0x12,0x13,0x14,0x15,0x16,0x17,
    0x23,0x24,0x25,0x26,0x27,
    0x34,0x35,0x36,0x37,
    0x45,0x46,0x47,
    0x56,0x57,
    0x67
};

__device__ __forceinline__ float fast_sqrt(float x) {
    float r;
    asm("sqrt.approx.f32 %0, %1;" : "=f"(r) : "f"(x));
    return r;
}

// (pd - td)^2 from Gram terms; accumulate when target dist in (0, CUTOFF]
__device__ __forceinline__ void pair_acc(
    const float4& pi, const float4& ti, const float4& pj, const float4& tj,
    float& num, float& den)
{
    float dp = pi.x*pj.x; dp = fmaf(pi.y, pj.y, dp); dp = fmaf(pi.z, pj.z, dp);
    float dt = ti.x*tj.x; dt = fmaf(ti.y, tj.y, dt); dt = fmaf(ti.z, tj.z, dt);
    float psq = fmaf(-2.f, dp, pi.w + pj.w);
    float tsq = fmaf(-2.f, dt, ti.w + tj.w);
    float pe = fmaxf(psq, EPSV);
    float v = (pe + tsq) - 2.f * fast_sqrt(pe * tsq);
    if (tsq > 0.f && tsq <= CUT2) { num += v; den += 1.f; }
}

__global__ void __launch_bounds__(256) fused_kernel(
    const float* __restrict__ lp, const float* __restrict__ lt,
    const float* __restrict__ scp, const float* __restrict__ sct,
    const unsigned int* __restrict__ lm, const unsigned int* __restrict__ am,
    float* __restrict__ out, int out_size)
{
    __shared__ float4 s_p[128];
    __shared__ float4 s_t[128];
    __shared__ float4 wr[8];
    __shared__ float bacc[4];
    __shared__ unsigned int s_islast;
    __shared__ float fin[3][2];
    __shared__ float sl[4];

    const int t = threadIdx.x;
    const int bid = blockIdx.x;
    const int lane = t & 31;

    if (bid < LIG_BLOCKS) {
        // ======================= ligand =======================
        const int b   = bid / LIG_BLOCKS_PER_B;
        const int sub = bid - b * LIG_BLOCKS_PER_B;
        const float* P = lp + (size_t)b * L * 3;
        const float* T = lt + (size_t)b * L * 3;
        const unsigned int* M = lm + (size_t)b * L;

        float num = 0.f, den = 0.f, se = 0.f, cnt = 0.f;

        if (sub < 28) {
            // ---- off-diagonal tile pair (a,bb): all 64x64 cross pairs ----
            const int code = d_tpairs[sub];
            const int ta = code >> 4, tb = code & 15;

            // fill 128 points (64 from each tile), 2 tensors -> 256 threads
            {
                const int pt   = t & 127;
                const int tens = t >> 7;
                const int gidx = ((pt < 64) ? ta : tb) * 64 + (pt & 63);
                const float* src = tens ? T : P;
                float x = src[gidx*3+0], y = src[gidx*3+1], z = src[gidx*3+2];
                if (tens && M[gidx] == 0u) x += 1e4f + 64.f * (float)gidx;
                float w = x*x + y*y + z*z;
                if (tens) s_t[pt] = make_float4(x, y, z, w);
                else      s_p[pt] = make_float4(x, y, z, w);
            }
            __syncthreads();

            // each thread: 4 i-points (tile a) in registers, 4 j-points (tile b)
            const int i0 = t & 15;
            float4 Pi[4], Ti[4];
            #pragma unroll
            for (int u = 0; u < 4; ++u) {
                Pi[u] = s_p[i0 + 16*u];
                Ti[u] = s_t[i0 + 16*u];
            }
            const int jb = 64 + (t >> 4);
            #pragma unroll
            for (int it = 0; it < 4; ++it) {
                float4 pj = s_p[jb + 16*it];
                float4 tj = s_t[jb + 16*it];
                #pragma unroll
                for (int u = 0; u < 4; ++u)
                    pair_acc(Pi[u], Ti[u], pj, tj, num, den);
            }
        } else {
            // ---- diagonal tile: within-tile pairs + coord MSE ----
            const int ta = sub - 28;
            if (t < 128) {
                const int pt   = t & 63;
                const int tens = t >> 6;
                const int gidx = ta * 64 + pt;
                const float* src = tens ? T : P;
                float x = src[gidx*3+0], y = src[gidx*3+1], z = src[gidx*3+2];
                if (tens && M[gidx] == 0u) x += 1e4f + 64.f * (float)gidx;
                float w = x*x + y*y + z*z;
                if (tens) s_t[pt] = make_float4(x, y, z, w);
                else      s_p[pt] = make_float4(x, y, z, w);
            }
            __syncthreads();

            if (t < 64 && M[ta*64 + t] != 0u) {   // st untouched when mask=1
                float4 p4 = s_p[t], t4 = s_t[t];
                float dx = p4.x - t4.x, dy = p4.y - t4.y, dz = p4.z - t4.z;
                se  = dx*dx + dy*dy + dz*dz;
                cnt = 1.f;
            }

            // round-robin within 64: k=1..31 all i, k=32 for i<32
            const int i   = t & 63;
            const int off = t >> 6;
            const float4 pi = s_p[i];
            const float4 ti = s_t[i];
            #pragma unroll
            for (int k = 1 + off; k <= 32; k += 4) {
                if (k == 32 && i >= 32) break;
                int j = (i + k) & 63;
                pair_acc(pi, ti, s_p[j], s_t[j], num, den);
            }
        }

        // block reduce 4 vars -> per-batch atomics
        #pragma unroll
        for (int s = 16; s > 0; s >>= 1) {
            num += __shfl_down_sync(FULLMASK, num, s);
            den += __shfl_down_sync(FULLMASK, den, s);
            se  += __shfl_down_sync(FULLMASK, se,  s);
            cnt += __shfl_down_sync(FULLMASK, cnt, s);
        }
        if (lane == 0) wr[t >> 5] = make_float4(num, den, se, cnt);
        __syncthreads();
        if (t < 8) {
            float4 v4 = wr[t];
            float a0 = v4.x, a1 = v4.y, a2 = v4.z, a3 = v4.w;
            #pragma unroll
            for (int s = 4; s > 0; s >>= 1) {
                a0 += __shfl_down_sync(0xffu, a0, s);
                a1 += __shfl_down_sync(0xffu, a1, s);
                a2 += __shfl_down_sync(0xffu, a2, s);
                a3 += __shfl_down_sync(0xffu, a3, s);
            }
            if (t == 0) {
                atomicAdd(&g_lig_num[b], a0);
                atomicAdd(&g_lig_den[b], a1);
                atomicAdd(&g_lig_se[b],  a2);
                atomicAdd(&g_lig_cnt[b], a3);
            }
        }
    } else {
        // ======================= sidechain (smem-free, shfl-based) =======================
        if (t < 4) bacc[t] = 0.f;
        __syncthreads();

        const int w = t >> 5;
        const int h = (lane >> 4);          // half-warp id: 0/1
        const int a = lane & 15;            // atom slot
        const bool av = a < A;
        const unsigned int g = (unsigned int)(bid - LIG_BLOCKS) * SC_GROUPS_PER_BLOCK + w * 2 + h;

        float px=0.f, py=0.f, pz=0.f, tx=0.f, ty=0.f, tz=0.f;
        float m = 0.f, mnum = 0.f;
        if (av) {
            const float* Pg = scp + (size_t)g * (A*3) + a*3;
            const float* Tg = sct + (size_t)g * (A*3) + a*3;
            px = Pg[0]; py = Pg[1]; pz = Pg[2];
            tx = Tg[0]; ty = Tg[1]; tz = Tg[2];
            m = (am[(size_t)g * A + a] != 0u) ? 1.f : 0.f;
            float dx = px - tx, dy = py - ty, dz = pz - tz;
            mnum = m * (dx*dx + dy*dy + dz*dz) * (1.f/3.f);
            if (m == 0.f) tx += 1e3f + 48.f * (float)a;   // push invalid targets apart
        }
        const unsigned int bal = __ballot_sync(FULLMASK, av && m != 0.f);
        float pw = px*px + py*py + pz*pz;
        float tw = tx*tx + ty*ty + tz*tz;

        float num = 0.f, den = 0.f;
        int j = a;
        #pragma unroll
        for (int d = 1; d <= 7; ++d) {
            j = (j + 1 == A) ? 0 : j + 1;          // (a+d) mod 14
            int src = (lane & 16) | j;
            float qx = __shfl_sync(FULLMASK, px, src);
            float qy = __shfl_sync(FULLMASK, py, src);
            float qz = __shfl_sync(FULLMASK, pz, src);
            float qw = __shfl_sync(FULLMASK, pw, src);
            float sx = __shfl_sync(FULLMASK, tx, src);
            float sy = __shfl_sync(FULLMASK, ty, src);
            float sz = __shfl_sync(FULLMASK, tz, src);
            float sw = __shfl_sync(FULLMASK, tw, src);
            float dp = px*qx; dp = fmaf(py, qy, dp); dp = fmaf(pz, qz, dp);
            float dt = tx*sx; dt = fmaf(ty, sy, dt); dt = fmaf(tz, sz, dt);
            float psq = fmaf(-2.f, dp, pw + qw);
            float tsq = fmaf(-2.f, dt, tw + sw);
            float pe = fmaxf(psq, EPSV);
            float v = (pe + tsq) - 2.f * fast_sqrt(pe * tsq);
            bool act = (d < 7) ? av : (a < 7);
            if (act && tsq > 0.f && tsq <= CUT2) { num += v; den += 1.f; }
        }

        // reduce within each 16-lane segment
        #pragma unroll
        for (int s = 8; s > 0; s >>= 1) {
            num  += __shfl_down_sync(FULLMASK, num,  s, 16);
            den  += __shfl_down_sync(FULLMASK, den,  s, 16);
            mnum += __shfl_down_sync(FULLMASK, mnum, s, 16);
        }
        float gs = 0.f, gc = 0.f;
        if (a == 0 && den > 0.f) { gs = num / den; gc = 1.f; }
        // fold half 1 into lane 0
        gs   += __shfl_down_sync(FULLMASK, gs,   16);
        gc   += __shfl_down_sync(FULLMASK, gc,   16);
        mnum += __shfl_down_sync(FULLMASK, mnum, 16);
        if (lane == 0) {
            float mden = (float)(__popc(bal & 0x3FFFu) + __popc((bal >> 16) & 0x3FFFu));
            atomicAdd(&bacc[0], gs);
            atomicAdd(&bacc[1], gc);
            atomicAdd(&bacc[2], mnum);
            atomicAdd(&bacc[3], mden);
        }
        __syncthreads();
        if (t < 4) atomicAdd(&g_slots[t][bid & (NSLOT - 1)], bacc[t]);
    }

    // ======================= last-block finalization =======================
    __threadfence();
    if (t == 0) s_islast = (atomicAdd(&g_ticket, 1u) == (unsigned)(GRID - 1)) ? 1u : 0u;
    __syncthreads();
    if (!s_islast) return;

    float lig = 0.f, ld = 0.f, has = 0.f;
    if (t < B) {
        float sev = __ldcg(&g_lig_se[t]);
        float cn  = __ldcg(&g_lig_cnt[t]);
        float nu  = __ldcg(&g_lig_num[t]);
        float de  = __ldcg(&g_lig_den[t]);
        lig = sev / (3.f * fmaxf(cn, 1.f));
        if (de > 0.f) { ld = nu / de; has = 1.f; }
    }
    #pragma unroll
    for (int s = 16; s > 0; s >>= 1) {
        lig += __shfl_down_sync(FULLMASK, lig, s);
        ld  += __shfl_down_sync(FULLMASK, ld,  s);
        has += __shfl_down_sync(FULLMASK, has, s);
    }
    if (lane == 0 && t < B) { fin[0][t>>5] = lig; fin[1][t>>5] = ld; fin[2][t>>5] = has; }

    if (t < NSLOT) {
        float s0 = __ldcg(&g_slots[0][t]);
        float s1 = __ldcg(&g_slots[1][t]);
        float s2 = __ldcg(&g_slots[2][t]);
        float s3 = __ldcg(&g_slots[3][t]);
        #pragma unroll
        for (int s = 16; s > 0; s >>= 1) {
            s0 += __shfl_down_sync(FULLMASK, s0, s);
            s1 += __shfl_down_sync(FULLMASK, s1, s);
            s2 += __shfl_down_sync(FULLMASK, s2, s);
            s3 += __shfl_down_sync(FULLMASK, s3, s);
        }
        if (t == 0) { sl[0] = s0; sl[1] = s1; sl[2] = s2; sl[3] = s3; }
    }
    __syncthreads();

    // reset scratch for next graph replay
    if (t < B) {
        g_lig_num[t] = 0.f; g_lig_den[t] = 0.f;
        g_lig_se[t]  = 0.f; g_lig_cnt[t] = 0.f;
    }
    if (t < 4 * NSLOT) g_slots[t >> 5][t & (NSLOT - 1)] = 0.f;
    if (t == 1) g_ticket = 0u;

    if (t == 0) {
        float ligand_loss = (fin[0][0] + fin[0][1]) * (1.f / 64.f);
        float hs = fin[2][0] + fin[2][1];
        float ligand_dist = (fin[1][0] + fin[1][1]) / fmaxf(hs, 1.f);
        float sc  = sl[2] / fmaxf(sl[3], 1.f);
        float scd = sl[0] / fmaxf(sl[1], 1.f);
        float total = ligand_loss + 0.2f * ligand_dist + 0.5f * sc + 0.1f * scd;
        for (int k = 0; k < out_size; ++k) out[k] = total;
    }
}

extern "C" void kernel_launch(void* const* d_in, const int* in_sizes, int n_in,
                              void* d_out, int out_size) {
    const float* lp  = (const float*)d_in[0];
    const float* lt  = (const float*)d_in[1];
    const float* scp = (const float*)d_in[2];
    const float* sct = (const float*)d_in[3];
    const unsigned int* lm = (const unsigned int*)d_in[4];
    const unsigned int* am = (const unsigned int*)d_in[5];
    (void)in_sizes; (void)n_in;

    fused_kernel<<<GRID, 256>>>(lp, lt, scp, sct, lm, am, (float*)d_out, out_size);
}

// round 6
// speedup vs baseline: 1.4053x; 1.1523x over previous
#include <cuda_runtime.h>

#define FULLMASK 0xffffffffu

constexpr int B = 64;
constexpr int L = 512;
constexpr int R = 1024;
constexpr int A = 14;
constexpr float EPSV = 1e-12f;
constexpr float CUT2 = 25.0f;     // CUTOFF^2

// ligand: per batch 28 off-diagonal tile-pair blocks + 8 diagonal blocks
constexpr int LIG_BLOCKS_PER_B = 36;
constexpr int LIG_BLOCKS = B * LIG_BLOCKS_PER_B;            // 2304
constexpr int SC_GROUPS_PER_BLOCK = 16;                     // 8 warps x 2 groups
constexpr int SC_BLOCKS = (B * R) / SC_GROUPS_PER_BLOCK;    // 4096
constexpr int GRID = LIG_BLOCKS + SC_BLOCKS;                // 6400
constexpr int NSLOT = 32;

// -------- persistent scratch (zeroed at load; finalizer re-zeros each run) --------
__device__ float g_lig_num[B];
__device__ float g_lig_den[B];
__device__ float g_lig_se[B];
__device__ float g_lig_cnt[B];
__device__ float g_slots[4][NSLOT];
__device__ unsigned int g_ticket;

// off-diagonal tile pair table: (a<<4)|b for 0<=a<b<8, 28 entries
__device__ const unsigned char d_tpairs[28] = {
    0x01,0x02,0x03,0x04,0x05,0x06,0x07,
    0x12,0x13,0x14,0x15,0x16,0x17,
    0x23,0x24,0x25,0x26,0x27,
    0x34,0x35,0x36,0x37,
    0x45,0x46,0x47,
    0x56,0x57,
    0x67
};

__device__ __forceinline__ float fast_sqrt(float x) {
    float r;
    asm("sqrt.approx.f32 %0, %1;" : "=f"(r) : "f"(x));
    return r;
}

// (pd - td)^2 from Gram terms; accumulate when target dist in (0, CUTOFF]
__device__ __forceinline__ void pair_acc(
    const float4& pi, const float4& ti, const float4& pj, const float4& tj,
    float& num, float& den)
{
    float dp = pi.x*pj.x; dp = fmaf(pi.y, pj.y, dp); dp = fmaf(pi.z, pj.z, dp);
    float dt = ti.x*tj.x; dt = fmaf(ti.y, tj.y, dt); dt = fmaf(ti.z, tj.z, dt);
    float psq = fmaf(-2.f, dp, pi.w + pj.w);
    float tsq = fmaf(-2.f, dt, ti.w + tj.w);
    float pe = fmaxf(psq, EPSV);
    float v = (pe + tsq) - 2.f * fast_sqrt(pe * tsq);
    if (tsq > 0.f && tsq <= CUT2) { num += v; den += 1.f; }
}

__global__ void __launch_bounds__(256) fused_kernel(
    const float* __restrict__ lp, const float* __restrict__ lt,
    const float* __restrict__ scp, const float* __restrict__ sct,
    const unsigned int* __restrict__ lm, const unsigned int* __restrict__ am,
    float* __restrict__ out, int out_size)
{
    __shared__ float4 s_p[128];
    __shared__ float4 s_t[128];
    __shared__ float4 wr[8];
    __shared__ float bacc[4];
    __shared__ unsigned int s_islast;
    __shared__ float fin[3][2];
    __shared__ float sl[4];

    const int t = threadIdx.x;
    const int bid = blockIdx.x;
    const int lane = t & 31;

    if (bid < LIG_BLOCKS) {
        // ======================= ligand =======================
        const int b   = bid / LIG_BLOCKS_PER_B;
        const int sub = bid - b * LIG_BLOCKS_PER_B;
        const float* P = lp + (size_t)b * L * 3;
        const float* T = lt + (size_t)b * L * 3;
        const unsigned int* M = lm + (size_t)b * L;

        float num = 0.f, den = 0.f, se = 0.f, cnt = 0.f;

        if (sub < 28) {
            // ---- off-diagonal tile pair (a,bb): all 64x64 cross pairs ----
            const int code = d_tpairs[sub];
            const int ta = code >> 4, tb = code & 15;

            // fill 128 points (64 from each tile), 2 tensors -> 256 threads
            {
                const int pt   = t & 127;
                const int tens = t >> 7;
                const int gidx = ((pt < 64) ? ta : tb) * 64 + (pt & 63);
                const float* src = tens ? T : P;
                float x = src[gidx*3+0], y = src[gidx*3+1], z = src[gidx*3+2];
                if (tens && M[gidx] == 0u) x += 1e4f + 64.f * (float)gidx;
                float w = x*x + y*y + z*z;
                if (tens) s_t[pt] = make_float4(x, y, z, w);
                else      s_p[pt] = make_float4(x, y, z, w);
            }
            __syncthreads();

            // each thread: 4 i-points (tile a) in registers, 4 j-points (tile b)
            const int i0 = t & 15;
            float4 Pi[4], Ti[4];
            #pragma unroll
            for (int u = 0; u < 4; ++u) {
                Pi[u] = s_p[i0 + 16*u];
                Ti[u] = s_t[i0 + 16*u];
            }
            const int jb = 64 + (t >> 4);
            #pragma unroll
            for (int it = 0; it < 4; ++it) {
                float4 pj = s_p[jb + 16*it];
                float4 tj = s_t[jb + 16*it];
                #pragma unroll
                for (int u = 0; u < 4; ++u)
                    pair_acc(Pi[u], Ti[u], pj, tj, num, den);
            }
        } else {
            // ---- diagonal tile: within-tile pairs + coord MSE ----
            const int ta = sub - 28;
            if (t < 128) {
                const int pt   = t & 63;
                const int tens = t >> 6;
                const int gidx = ta * 64 + pt;
                const float* src = tens ? T : P;
                float x = src[gidx*3+0], y = src[gidx*3+1], z = src[gidx*3+2];
                if (tens && M[gidx] == 0u) x += 1e4f + 64.f * (float)gidx;
                float w = x*x + y*y + z*z;
                if (tens) s_t[pt] = make_float4(x, y, z, w);
                else      s_p[pt] = make_float4(x, y, z, w);
            }
            __syncthreads();

            if (t < 64 && M[ta*64 + t] != 0u) {   // st untouched when mask=1
                float4 p4 = s_p[t], t4 = s_t[t];
                float dx = p4.x - t4.x, dy = p4.y - t4.y, dz = p4.z - t4.z;
                se  = dx*dx + dy*dy + dz*dz;
                cnt = 1.f;
            }

            // round-robin within 64: k=1..31 all i, k=32 for i<32
            const int i   = t & 63;
            const int off = t >> 6;
            const float4 pi = s_p[i];
            const float4 ti = s_t[i];
            #pragma unroll
            for (int k = 1 + off; k <= 32; k += 4) {
                if (k == 32 && i >= 32) break;
                int j = (i + k) & 63;
                pair_acc(pi, ti, s_p[j], s_t[j], num, den);
            }
        }

        // block reduce 4 vars -> per-batch atomics
        #pragma unroll
        for (int s = 16; s > 0; s >>= 1) {
            num += __shfl_down_sync(FULLMASK, num, s);
            den += __shfl_down_sync(FULLMASK, den, s);
            se  += __shfl_down_sync(FULLMASK, se,  s);
            cnt += __shfl_down_sync(FULLMASK, cnt, s);
        }
        if (lane == 0) wr[t >> 5] = make_float4(num, den, se, cnt);
        __syncthreads();
        if (t < 8) {
            float4 v4 = wr[t];
            float a0 = v4.x, a1 = v4.y, a2 = v4.z, a3 = v4.w;
            #pragma unroll
            for (int s = 4; s > 0; s >>= 1) {
                a0 += __shfl_down_sync(0xffu, a0, s);
                a1 += __shfl_down_sync(0xffu, a1, s);
                a2 += __shfl_down_sync(0xffu, a2, s);
                a3 += __shfl_down_sync(0xffu, a3, s);
            }
            if (t == 0) {
                atomicAdd(&g_lig_num[b], a0);
                atomicAdd(&g_lig_den[b], a1);
                atomicAdd(&g_lig_se[b],  a2);
                atomicAdd(&g_lig_cnt[b], a3);
            }
        }
    } else {
        // ======================= sidechain (smem-free, shfl-based) =======================
        if (t < 4) bacc[t] = 0.f;
        __syncthreads();

        const int w = t >> 5;
        const int h = (lane >> 4);          // half-warp id: 0/1
        const int a = lane & 15;            // atom slot
        const bool av = a < A;
        const unsigned int g = (unsigned int)(bid - LIG_BLOCKS) * SC_GROUPS_PER_BLOCK + w * 2 + h;

        float px=0.f, py=0.f, pz=0.f, tx=0.f, ty=0.f, tz=0.f;
        float m = 0.f, mnum = 0.f;
        if (av) {
            const float* Pg = scp + (size_t)g * (A*3) + a*3;
            const float* Tg = sct + (size_t)g * (A*3) + a*3;
            px = Pg[0]; py = Pg[1]; pz = Pg[2];
            tx = Tg[0]; ty = Tg[1]; tz = Tg[2];
            m = (am[(size_t)g * A + a] != 0u) ? 1.f : 0.f;
            float dx = px - tx, dy = py - ty, dz = pz - tz;
            mnum = m * (dx*dx + dy*dy + dz*dz) * (1.f/3.f);
            if (m == 0.f) tx += 1e3f + 48.f * (float)a;   // push invalid targets apart
        }
        const unsigned int bal = __ballot_sync(FULLMASK, av && m != 0.f);
        float pw = px*px + py*py + pz*pz;
        float tw = tx*tx + ty*ty + tz*tz;

        float num = 0.f, den = 0.f;
        int j = a;
        #pragma unroll
        for (int d = 1; d <= 7; ++d) {
            j = (j + 1 == A) ? 0 : j + 1;          // (a+d) mod 14
            int src = (lane & 16) | j;
            float qx = __shfl_sync(FULLMASK, px, src);
            float qy = __shfl_sync(FULLMASK, py, src);
            float qz = __shfl_sync(FULLMASK, pz, src);
            float qw = __shfl_sync(FULLMASK, pw, src);
            float sx = __shfl_sync(FULLMASK, tx, src);
            float sy = __shfl_sync(FULLMASK, ty, src);
            float sz = __shfl_sync(FULLMASK, tz, src);
            float sw = __shfl_sync(FULLMASK, tw, src);
            float dp = px*qx; dp = fmaf(py, qy, dp); dp = fmaf(pz, qz, dp);
            float dt = tx*sx; dt = fmaf(ty, sy, dt); dt = fmaf(tz, sz, dt);
            float psq = fmaf(-2.f, dp, pw + qw);
            float tsq = fmaf(-2.f, dt, tw + sw);
            float pe = fmaxf(psq, EPSV);
            float v = (pe + tsq) - 2.f * fast_sqrt(pe * tsq);
            bool act = (d < 7) ? av : (a < 7);
            if (act && tsq > 0.f && tsq <= CUT2) { num += v; den += 1.f; }
        }

        // reduce within each 16-lane segment
        #pragma unroll
        for (int s = 8; s > 0; s >>= 1) {
            num  += __shfl_down_sync(FULLMASK, num,  s, 16);
            den  += __shfl_down_sync(FULLMASK, den,  s, 16);
            mnum += __shfl_down_sync(FULLMASK, mnum, s, 16);
        }
        float gs = 0.f, gc = 0.f;
        if (a == 0 && den > 0.f) { gs = num / den; gc = 1.f; }
        // fold half 1 into lane 0
        gs   += __shfl_down_sync(FULLMASK, gs,   16);
        gc   += __shfl_down_sync(FULLMASK, gc,   16);
        mnum += __shfl_down_sync(FULLMASK, mnum, 16);
        if (lane == 0) {
            float mden = (float)(__popc(bal & 0x3FFFu) + __popc((bal >> 16) & 0x3FFFu));
            atomicAdd(&bacc[0], gs);
            atomicAdd(&bacc[1], gc);
            atomicAdd(&bacc[2], mnum);
            atomicAdd(&bacc[3], mden);
        }
        __syncthreads();
        if (t < 4) atomicAdd(&g_slots[t][bid & (NSLOT - 1)], bacc[t]);
    }

    // ======================= last-block finalization =======================
    __threadfence();
    if (t == 0) s_islast = (atomicAdd(&g_ticket, 1u) == (unsigned)(GRID - 1)) ? 1u : 0u;
    __syncthreads();
    if (!s_islast) return;

    float lig = 0.f, ld = 0.f, has = 0.f;
    if (t < B) {
        float sev = __ldcg(&g_lig_se[t]);
        float cn  = __ldcg(&g_lig_cnt[t]);
        float nu  = __ldcg(&g_lig_num[t]);
        float de  = __ldcg(&g_lig_den[t]);
        lig = sev / (3.f * fmaxf(cn, 1.f));
        if (de > 0.f) { ld = nu / de; has = 1.f; }
    }
    #pragma unroll
    for (int s = 16; s > 0; s >>= 1) {
        lig += __shfl_down_sync(FULLMASK, lig, s);
        ld  += __shfl_down_sync(FULLMASK, ld,  s);
        has += __shfl_down_sync(FULLMASK, has, s);
    }
    if (lane == 0 && t < B) { fin[0][t>>5] = lig; fin[1][t>>5] = ld; fin[2][t>>5] = has; }

    if (t < NSLOT) {
        float s0 = __ldcg(&g_slots[0][t]);
        float s1 = __ldcg(&g_slots[1][t]);
        float s2 = __ldcg(&g_slots[2][t]);
        float s3 = __ldcg(&g_slots[3][t]);
        #pragma unroll
        for (int s = 16; s > 0; s >>= 1) {
            s0 += __shfl_down_sync(FULLMASK, s0, s);
            s1 += __shfl_down_sync(FULLMASK, s1, s);
            s2 += __shfl_down_sync(FULLMASK, s2, s);
            s3 += __shfl_down_sync(FULLMASK, s3, s);
        }
        if (t == 0) { sl[0] = s0; sl[1] = s1; sl[2] = s2; sl[3] = s3; }
    }
    __syncthreads();

    // reset scratch for next graph replay
    if (t < B) {
        g_lig_num[t] = 0.f; g_lig_den[t] = 0.f;
        g_lig_se[t]  = 0.f; g_lig_cnt[t] = 0.f;
    }
    if (t < 4 * NSLOT) g_slots[t >> 5][t & (NSLOT - 1)] = 0.f;
    if (t == 1) g_ticket = 0u;

    if (t == 0) {
        float ligand_loss = (fin[0][0] + fin[0][1]) * (1.f / 64.f);
        float hs = fin[2][0] + fin[2][1];
        float ligand_dist = (fin[1][0] + fin[1][1]) / fmaxf(hs, 1.f);
        float sc  = sl[2] / fmaxf(sl[3], 1.f);
        float scd = sl[0] / fmaxf(sl[1], 1.f);
        float total = ligand_loss + 0.2f * ligand_dist + 0.5f * sc + 0.1f * scd;
        for (int k = 0; k < out_size; ++k) out[k] = total;
    }
}

extern "C" void kernel_launch(void* const* d_in, const int* in_sizes, int n_in,
                              void* d_out, int out_size) {
    const float* lp  = (const float*)d_in[0];
    const float* lt  = (const float*)d_in[1];
    const float* scp = (const float*)d_in[2];
    const float* sct = (const float*)d_in[3];
    const unsigned int* lm = (const unsigned int*)d_in[4];
    const unsigned int* am = (const unsigned int*)d_in[5];
    (void)in_sizes; (void)n_in;

    fused_kernel<<<GRID, 256>>>(lp, lt, scp, sct, lm, am, (float*)d_out, out_size);
}